// round 7
// baseline (speedup 1.0000x reference)
#include <cuda_runtime.h>
#include <cstdint>
#include <cfloat>

#define Sdim 512
#define Bdim 64
#define Hdim 1024
#define EHdim 1024
#define Vdim 50257
#define Ktot 2048              // H + EH

// ---- scratch (no allocations allowed) ----
__device__ float g_h[Bdim * Hdim];
__device__ float g_u[Bdim * EHdim];
__device__ float g_scores[Bdim * Sdim];
__device__ float g_w[Bdim * Sdim];
__device__ float g_y[Bdim * Ktot];   // [h | context], K-major per b

// ============================================================================
// sm_80-class PTX helpers (safe under .target sm_103 — no 'a' features)
// ============================================================================
__device__ __forceinline__ uint32_t smem_to_u32(const void* p) {
    uint32_t a;
    asm("{ .reg .u64 t; cvta.to.shared.u64 t, %1; cvt.u32.u64 %0, t; }" : "=r"(a) : "l"(p));
    return a;
}
__device__ __forceinline__ void cp_async16(uint32_t dst, const void* src) {
    asm volatile("cp.async.ca.shared.global [%0], [%1], 16;" :: "r"(dst), "l"(src));
}
__device__ __forceinline__ void cp_async16_zfill(uint32_t dst, const void* src, int src_bytes) {
    asm volatile("cp.async.ca.shared.global [%0], [%1], 16, %2;"
                 :: "r"(dst), "l"(src), "r"(src_bytes));
}
#define CP_COMMIT() asm volatile("cp.async.commit_group;" ::: "memory")
#define CP_WAIT(n)  asm volatile("cp.async.wait_group %0;" :: "n"(n) : "memory")

__device__ __forceinline__ void mma_tf32(float* c, const uint32_t* a, const uint32_t* b) {
    asm volatile("mma.sync.aligned.m16n8k8.row.col.f32.tf32.tf32.f32 "
        "{%0,%1,%2,%3}, {%4,%5,%6,%7}, {%8,%9}, {%0,%1,%2,%3};"
        : "+f"(c[0]), "+f"(c[1]), "+f"(c[2]), "+f"(c[3])
        : "r"(a[0]), "r"(a[1]), "r"(a[2]), "r"(a[3]), "r"(b[0]), "r"(b[1]));
}

// ---------------------------------------------------------------------------
// K1: GRU with h0=0 => gh = b_hh. Tiled GEMM: block = 8 j x 64 b, K via smem.
// ---------------------------------------------------------------------------
__global__ __launch_bounds__(256) void gru_kernel(
    const float* __restrict__ x, const float* __restrict__ W_ih,
    const float* __restrict__ b_ih, const float* __restrict__ b_hh,
    float* __restrict__ out_h)
{
    __shared__ float w_s[24][33];
    __shared__ float x_s[32][65];

    const int t  = threadIdx.x;
    const int j0 = blockIdx.x * 8;
    const int jj = t & 7;
    const int bg = t >> 3;

    float a00 = 0.f, a01 = 0.f, a10 = 0.f, a11 = 0.f, a20 = 0.f, a21 = 0.f;

    for (int k0 = 0; k0 < Hdim; k0 += 32) {
        if (t < 192) {
            int r = t >> 3, f4 = t & 7;
            int g = r >> 3, jl = r & 7;
            float4 w = *(const float4*)(W_ih + (size_t)(g * Hdim + j0 + jl) * Hdim + k0 + 4 * f4);
            w_s[r][4 * f4 + 0] = w.x; w_s[r][4 * f4 + 1] = w.y;
            w_s[r][4 * f4 + 2] = w.z; w_s[r][4 * f4 + 3] = w.w;
        }
        #pragma unroll
        for (int i = 0; i < 2; i++) {
            int idx = t + 256 * i;
            int b = idx >> 3, q = idx & 7;
            float4 xv = *(const float4*)(x + (size_t)b * Hdim + k0 + 4 * q);
            x_s[4 * q + 0][b] = xv.x; x_s[4 * q + 1][b] = xv.y;
            x_s[4 * q + 2][b] = xv.z; x_s[4 * q + 3][b] = xv.w;
        }
        __syncthreads();
        #pragma unroll
        for (int kk = 0; kk < 32; kk++) {
            float x0 = x_s[kk][2 * bg], x1 = x_s[kk][2 * bg + 1];
            float w0 = w_s[jj][kk], w1 = w_s[8 + jj][kk], w2 = w_s[16 + jj][kk];
            a00 += w0 * x0; a01 += w0 * x1;
            a10 += w1 * x0; a11 += w1 * x1;
            a20 += w2 * x0; a21 += w2 * x1;
        }
        __syncthreads();
    }

    int j = j0 + jj;
    float bi0 = b_ih[j], bi1 = b_ih[Hdim + j], bi2 = b_ih[2 * Hdim + j];
    float bh0 = b_hh[j], bh1 = b_hh[Hdim + j], bh2 = b_hh[2 * Hdim + j];
    #pragma unroll
    for (int q = 0; q < 2; q++) {
        int b = 2 * bg + q;
        float xr = (q ? a01 : a00) + bi0;
        float xz = (q ? a11 : a10) + bi1;
        float xn = (q ? a21 : a20) + bi2;
        float r = 1.f / (1.f + expf(-(xr + bh0)));
        float z = 1.f / (1.f + expf(-(xz + bh1)));
        float n = tanhf(xn + r * bh2);
        float h = (1.f - z) * n;               // + z*h0, h0 = 0
        g_h[b * Hdim + j] = h;
        g_y[(size_t)b * Ktot + j] = h;
        out_h[b * Hdim + j] = h;
    }
}

// ---------------------------------------------------------------------------
// K2: u[b,e] = sum_h g_h[b,h] * attn_W[h, Hdim + e]
// ---------------------------------------------------------------------------
__global__ __launch_bounds__(256) void u_kernel(const float* __restrict__ attn_W)
{
    int idx = blockIdx.x * blockDim.x + threadIdx.x;   // 65536
    int e = idx & 1023;
    int b = idx >> 10;
    const float* W = attn_W + Hdim + e;
    const float* hb = g_h + b * Hdim;
    float a0 = 0.f, a1 = 0.f;
    #pragma unroll 8
    for (int hh = 0; hh < Hdim; hh += 2) {
        a0 += hb[hh]     * W[(size_t)hh * (Hdim + EHdim)];
        a1 += hb[hh + 1] * W[(size_t)(hh + 1) * (Hdim + EHdim)];
    }
    g_u[b * EHdim + e] = a0 + a1;
}

// ---------------------------------------------------------------------------
// K3: scores[b,s] = dot(enc[s,b,:], u[b,:])
// ---------------------------------------------------------------------------
__global__ __launch_bounds__(256) void scores_kernel(const float* __restrict__ enc)
{
    int gw   = (blockIdx.x * blockDim.x + threadIdx.x) >> 5;
    int lane = threadIdx.x & 31;
    int b = gw >> 9;
    int s = gw & 511;
    const float4* ev = (const float4*)(enc + (size_t)s * (Bdim * EHdim) + (size_t)b * EHdim);
    const float4* uv = (const float4*)(g_u + (size_t)b * EHdim);
    float acc = 0.f;
    #pragma unroll 4
    for (int t = lane; t < EHdim / 4; t += 32) {
        float4 e4 = ev[t], u4 = uv[t];
        acc += e4.x*u4.x + e4.y*u4.y + e4.z*u4.z + e4.w*u4.w;
    }
    #pragma unroll
    for (int o = 16; o; o >>= 1) acc += __shfl_xor_sync(0xffffffffu, acc, o);
    if (lane == 0) g_scores[b * Sdim + s] = acc;
}

// ---------------------------------------------------------------------------
// K4: softmax over s (512) per b
// ---------------------------------------------------------------------------
__global__ __launch_bounds__(256) void softmax_kernel(float* __restrict__ out_attn)
{
    int b = blockIdx.x, tid = threadIdx.x;
    __shared__ float red[8];
    __shared__ float bcast[2];

    float s0 = g_scores[b * Sdim + tid];
    float s1 = g_scores[b * Sdim + 256 + tid];

    float m = fmaxf(s0, s1);
    #pragma unroll
    for (int o = 16; o; o >>= 1) m = fmaxf(m, __shfl_xor_sync(0xffffffffu, m, o));
    if ((tid & 31) == 0) red[tid >> 5] = m;
    __syncthreads();
    if (tid < 32) {
        float v = (tid < 8) ? red[tid] : -FLT_MAX;
        #pragma unroll
        for (int o = 4; o; o >>= 1) v = fmaxf(v, __shfl_xor_sync(0xffffffffu, v, o));
        if (tid == 0) bcast[0] = v;
    }
    __syncthreads();
    float bm = bcast[0];

    float e0 = expf(s0 - bm), e1 = expf(s1 - bm);
    float sum = e0 + e1;
    #pragma unroll
    for (int o = 16; o; o >>= 1) sum += __shfl_xor_sync(0xffffffffu, sum, o);
    if ((tid & 31) == 0) red[tid >> 5] = sum;
    __syncthreads();
    if (tid < 32) {
        float v = (tid < 8) ? red[tid] : 0.f;
        #pragma unroll
        for (int o = 4; o; o >>= 1) v += __shfl_xor_sync(0xffffffffu, v, o);
        if (tid == 0) bcast[1] = v;
    }
    __syncthreads();
    float inv = 1.f / bcast[1];

    float w0 = e0 * inv, w1 = e1 * inv;
    g_w[b * Sdim + tid]       = w0;
    g_w[b * Sdim + 256 + tid] = w1;
    out_attn[b * Sdim + tid]       = w0;
    out_attn[b * Sdim + 256 + tid] = w1;
}

// ---------------------------------------------------------------------------
// K5: context[b,e] = sum_s w[b,s] * enc[s,b,e]
// ---------------------------------------------------------------------------
__global__ __launch_bounds__(256) void context_kernel(const float* __restrict__ enc)
{
    int idx = blockIdx.x * blockDim.x + threadIdx.x;   // 65536
    int b = idx >> 10;
    int e = idx & 1023;
    const float* wrow = g_w + b * Sdim;
    const float* ep   = enc + (size_t)b * EHdim + e;
    float a0 = 0.f, a1 = 0.f;
    #pragma unroll 4
    for (int s = 0; s < Sdim; s += 2) {
        a0 += wrow[s]     * ep[(size_t)s * (Bdim * EHdim)];
        a1 += wrow[s + 1] * ep[(size_t)(s + 1) * (Bdim * EHdim)];
    }
    g_y[(size_t)b * Ktot + Hdim + e] = a0 + a1;
}

// ---------------------------------------------------------------------------
// K6: dec = y @ out_W^T + out_b via mma.sync tf32 (m16n8k8), cp.async pipeline.
// CTA: D[256 v x 64 b]; 8 warps as 4(M) x 2(N); warp tile 64x32 (4 mt x 4 nt).
// K = 2048 in 64 chunks of 32, double-buffered; 2 CTAs/SM; grid = 197 = 1 wave.
// Logical-k remap: fragment k (tig, tig+4) <- global k (2*tig, 2*tig+1), same
// map for A and B, so every fragment pair is one aligned LDS.64.
// RSTR=40 floats -> row stride 8 mod 32 word-banks: conflict-free LDS.64/STS.
// tf32 operands are raw fp32 bits (HW truncation) — no cvt in hot loop.
// ---------------------------------------------------------------------------
#define DEC_M     256
#define DEC_KC    32
#define DEC_NCH   (Ktot / DEC_KC)       // 64
#define RSTR      40                    // padded row stride (floats)
#define AWORDS    (DEC_M * RSTR)        // 10240
#define BWORDS    (Bdim * RSTR)         // 2560
#define BUFWORDS  (AWORDS + BWORDS)     // 12800
#define DEC_SMEM  (2 * BUFWORDS * 4)    // 102400 bytes

__global__ __launch_bounds__(256, 2) void dec_kernel(
    const float* __restrict__ out_W, const float* __restrict__ out_b,
    float* __restrict__ dec)
{
    extern __shared__ float smf[];
    const uint32_t sb = smem_to_u32(smf);

    const int tx   = threadIdx.x;
    const int wid  = tx >> 5;
    const int lane = tx & 31;
    const int gid  = lane >> 2;      // 0..7
    const int tig  = lane & 3;       // 0..3
    const int wm   = wid & 3;        // 4 warps across M
    const int wn   = wid >> 2;       // 2 warps across N
    const int rb   = wm * 64;        // warp M base (64 rows)
    const int bb   = wn * 32;        // warp N base (32 cols)
    const int vb   = blockIdx.x * DEC_M;

    float acc[4][4][4];
    #pragma unroll
    for (int mt = 0; mt < 4; mt++)
        #pragma unroll
        for (int nt = 0; nt < 4; nt++)
            #pragma unroll
            for (int i = 0; i < 4; i++) acc[mt][nt][i] = 0.f;

    auto stage = [&](int c, int buf) {
        const int k0 = c * DEC_KC;
        const uint32_t base = sb + (uint32_t)buf * BUFWORDS * 4;
        #pragma unroll
        for (int i = 0; i < 8; i++) {            // A: 256 rows x 8 quads
            int idx = tx + 256 * i;
            int r = idx >> 3, q = idx & 7;
            int v = vb + r;
            int vc = v < Vdim ? v : (Vdim - 1);
            const float* src = out_W + (size_t)vc * Ktot + k0 + 4 * q;
            uint32_t dst = base + (uint32_t)(r * RSTR + 4 * q) * 4;
            cp_async16_zfill(dst, src, v < Vdim ? 16 : 0);
        }
        #pragma unroll
        for (int i = 0; i < 2; i++) {            // B: 64 rows x 8 quads
            int idx = tx + 256 * i;
            int r = idx >> 3, q = idx & 7;
            const float* src = g_y + (size_t)r * Ktot + k0 + 4 * q;
            uint32_t dst = base + (uint32_t)(AWORDS + r * RSTR + 4 * q) * 4;
            cp_async16(dst, src);
        }
    };

    stage(0, 0);
    CP_COMMIT();

    for (int c = 0; c < DEC_NCH; c++) {
        const int buf = c & 1;
        if (c + 1 < DEC_NCH) {
            stage(c + 1, (c + 1) & 1);
            CP_COMMIT();
            CP_WAIT(1);
        } else {
            CP_WAIT(0);
        }
        __syncthreads();

        const float* As = smf + buf * BUFWORDS;
        const float* Bs = As + AWORDS;
        #pragma unroll
        for (int ks = 0; ks < 4; ks++) {
            const int k = ks * 8;
            uint32_t a[4][4], bf[4][2];
            #pragma unroll
            for (int mt = 0; mt < 4; mt++) {
                int row = rb + mt * 16 + gid;
                uint2 lo = *(const uint2*)(As + row * RSTR + k + 2 * tig);
                uint2 hi = *(const uint2*)(As + (row + 8) * RSTR + k + 2 * tig);
                a[mt][0] = lo.x; a[mt][2] = lo.y;   // logical k=tig, tig+4
                a[mt][1] = hi.x; a[mt][3] = hi.y;
            }
            #pragma unroll
            for (int nt = 0; nt < 4; nt++) {
                int bc = bb + nt * 8 + gid;
                uint2 bv = *(const uint2*)(Bs + bc * RSTR + k + 2 * tig);
                bf[nt][0] = bv.x; bf[nt][1] = bv.y;
            }
            #pragma unroll
            for (int mt = 0; mt < 4; mt++)
                #pragma unroll
                for (int nt = 0; nt < 4; nt++)
                    mma_tf32(acc[mt][nt], a[mt], bf[nt]);
        }
        __syncthreads();
    }

    // ---- epilogue ----
    #pragma unroll
    for (int mt = 0; mt < 4; mt++) {
        int v0 = vb + rb + mt * 16 + gid;
        int v1 = v0 + 8;
        float bias0 = (v0 < Vdim) ? out_b[v0] : 0.f;
        float bias1 = (v1 < Vdim) ? out_b[v1] : 0.f;
        #pragma unroll
        for (int nt = 0; nt < 4; nt++) {
            int b0 = bb + nt * 8 + 2 * tig;
            int b1 = b0 + 1;
            if (v0 < Vdim) {
                dec[(size_t)b0 * Vdim + v0] = acc[mt][nt][0] + bias0;
                dec[(size_t)b1 * Vdim + v0] = acc[mt][nt][1] + bias0;
            }
            if (v1 < Vdim) {
                dec[(size_t)b0 * Vdim + v1] = acc[mt][nt][2] + bias1;
                dec[(size_t)b1 * Vdim + v1] = acc[mt][nt][3] + bias1;
            }
        }
    }
}

// ---------------------------------------------------------------------------
// K7: in-place log_softmax over V per row b
// ---------------------------------------------------------------------------
__global__ __launch_bounds__(512) void logsoftmax_kernel(float* __restrict__ dec)
{
    int b = blockIdx.x, tid = threadIdx.x;
    float* row = dec + (size_t)b * Vdim;
    __shared__ float red[16];
    __shared__ float bcast;

    float m = -FLT_MAX;
    for (int i = tid; i < Vdim; i += 512) m = fmaxf(m, row[i]);
    #pragma unroll
    for (int o = 16; o; o >>= 1) m = fmaxf(m, __shfl_xor_sync(0xffffffffu, m, o));
    if ((tid & 31) == 0) red[tid >> 5] = m;
    __syncthreads();
    if (tid < 32) {
        float v = (tid < 16) ? red[tid] : -FLT_MAX;
        #pragma unroll
        for (int o = 8; o; o >>= 1) v = fmaxf(v, __shfl_xor_sync(0xffffffffu, v, o));
        if (tid == 0) bcast = v;
    }
    __syncthreads();
    float bm = bcast;
    __syncthreads();

    float s = 0.f;
    for (int i = tid; i < Vdim; i += 512) s += expf(row[i] - bm);
    #pragma unroll
    for (int o = 16; o; o >>= 1) s += __shfl_xor_sync(0xffffffffu, s, o);
    if ((tid & 31) == 0) red[tid >> 5] = s;
    __syncthreads();
    if (tid < 32) {
        float v = (tid < 16) ? red[tid] : 0.f;
        #pragma unroll
        for (int o = 8; o; o >>= 1) v += __shfl_xor_sync(0xffffffffu, v, o);
        if (tid == 0) bcast = v;
    }
    __syncthreads();
    float lse = bm + logf(bcast);

    for (int i = tid; i < Vdim; i += 512) row[i] -= lse;
}

// ---------------------------------------------------------------------------
extern "C" void kernel_launch(void* const* d_in, const int* in_sizes, int n_in,
                              void* d_out, int out_size)
{
    const float* x      = (const float*)d_in[0];
    const float* enc    = (const float*)d_in[1];
    const float* W_ih   = (const float*)d_in[3];
    const float* b_ih   = (const float*)d_in[5];
    const float* b_hh   = (const float*)d_in[6];
    const float* attn_W = (const float*)d_in[7];
    const float* out_W  = (const float*)d_in[9];
    const float* out_b  = (const float*)d_in[10];

    float* out = (float*)d_out;
    const size_t OFF_H    = (size_t)Bdim * Vdim;
    const size_t OFF_ATTN = OFF_H + (size_t)Bdim * Hdim;

    cudaFuncSetAttribute(dec_kernel, cudaFuncAttributeMaxDynamicSharedMemorySize, DEC_SMEM);

    gru_kernel<<<128, 256>>>(x, W_ih, b_ih, b_hh, out + OFF_H);
    u_kernel<<<256, 256>>>(attn_W);
    scores_kernel<<<4096, 256>>>(enc);
    softmax_kernel<<<Bdim, 256>>>(out + OFF_ATTN);
    context_kernel<<<256, 256>>>(enc);
    dec_kernel<<<(Vdim + DEC_M - 1) / DEC_M, 256, DEC_SMEM>>>(out_W, out_b, out);
    logsoftmax_kernel<<<Bdim, 512>>>(out);
}

// round 8
// speedup vs baseline: 1.3118x; 1.3118x over previous
#include <cuda_runtime.h>
#include <cstdint>
#include <cfloat>

#define Sdim 512
#define Bdim 64
#define Hdim 1024
#define EHdim 1024
#define Vdim 50257
#define Ktot 2048              // H + EH

// ---- scratch (no allocations allowed) ----
__device__ float g_h[Bdim * Hdim];
__device__ float g_u[Bdim * EHdim];
__device__ float g_scores[Bdim * Sdim];
__device__ float g_w[Bdim * Sdim];
__device__ float g_y[Bdim * Ktot];   // [h | context], K-major per b

// ============================================================================
// sm_80-class PTX helpers (safe under .target sm_103 — no 'a' features)
// ============================================================================
__device__ __forceinline__ uint32_t smem_to_u32(const void* p) {
    uint32_t a;
    asm("{ .reg .u64 t; cvta.to.shared.u64 t, %1; cvt.u32.u64 %0, t; }" : "=r"(a) : "l"(p));
    return a;
}
__device__ __forceinline__ void cp_async16(uint32_t dst, const void* src) {
    asm volatile("cp.async.ca.shared.global [%0], [%1], 16;" :: "r"(dst), "l"(src));
}
__device__ __forceinline__ void cp_async16_zfill(uint32_t dst, const void* src, int src_bytes) {
    asm volatile("cp.async.ca.shared.global [%0], [%1], 16, %2;"
                 :: "r"(dst), "l"(src), "r"(src_bytes));
}
#define CP_COMMIT() asm volatile("cp.async.commit_group;" ::: "memory")
#define CP_WAIT(n)  asm volatile("cp.async.wait_group %0;" :: "n"(n) : "memory")

__device__ __forceinline__ void mma_tf32(float* c, const uint32_t* a, const uint32_t* b) {
    asm volatile("mma.sync.aligned.m16n8k8.row.col.f32.tf32.tf32.f32 "
        "{%0,%1,%2,%3}, {%4,%5,%6,%7}, {%8,%9}, {%0,%1,%2,%3};"
        : "+f"(c[0]), "+f"(c[1]), "+f"(c[2]), "+f"(c[3])
        : "r"(a[0]), "r"(a[1]), "r"(a[2]), "r"(a[3]), "r"(b[0]), "r"(b[1]));
}

// ---------------------------------------------------------------------------
// K1: GRU with h0=0 => gh = b_hh. Tiled GEMM: block = 8 j x 64 b, K via smem.
// ---------------------------------------------------------------------------
__global__ __launch_bounds__(256) void gru_kernel(
    const float* __restrict__ x, const float* __restrict__ W_ih,
    const float* __restrict__ b_ih, const float* __restrict__ b_hh,
    float* __restrict__ out_h)
{
    __shared__ float w_s[24][33];
    __shared__ float x_s[32][65];

    const int t  = threadIdx.x;
    const int j0 = blockIdx.x * 8;
    const int jj = t & 7;
    const int bg = t >> 3;

    float a00 = 0.f, a01 = 0.f, a10 = 0.f, a11 = 0.f, a20 = 0.f, a21 = 0.f;

    for (int k0 = 0; k0 < Hdim; k0 += 32) {
        if (t < 192) {
            int r = t >> 3, f4 = t & 7;
            int g = r >> 3, jl = r & 7;
            float4 w = *(const float4*)(W_ih + (size_t)(g * Hdim + j0 + jl) * Hdim + k0 + 4 * f4);
            w_s[r][4 * f4 + 0] = w.x; w_s[r][4 * f4 + 1] = w.y;
            w_s[r][4 * f4 + 2] = w.z; w_s[r][4 * f4 + 3] = w.w;
        }
        #pragma unroll
        for (int i = 0; i < 2; i++) {
            int idx = t + 256 * i;
            int b = idx >> 3, q = idx & 7;
            float4 xv = *(const float4*)(x + (size_t)b * Hdim + k0 + 4 * q);
            x_s[4 * q + 0][b] = xv.x; x_s[4 * q + 1][b] = xv.y;
            x_s[4 * q + 2][b] = xv.z; x_s[4 * q + 3][b] = xv.w;
        }
        __syncthreads();
        #pragma unroll
        for (int kk = 0; kk < 32; kk++) {
            float x0 = x_s[kk][2 * bg], x1 = x_s[kk][2 * bg + 1];
            float w0 = w_s[jj][kk], w1 = w_s[8 + jj][kk], w2 = w_s[16 + jj][kk];
            a00 += w0 * x0; a01 += w0 * x1;
            a10 += w1 * x0; a11 += w1 * x1;
            a20 += w2 * x0; a21 += w2 * x1;
        }
        __syncthreads();
    }

    int j = j0 + jj;
    float bi0 = b_ih[j], bi1 = b_ih[Hdim + j], bi2 = b_ih[2 * Hdim + j];
    float bh0 = b_hh[j], bh1 = b_hh[Hdim + j], bh2 = b_hh[2 * Hdim + j];
    #pragma unroll
    for (int q = 0; q < 2; q++) {
        int b = 2 * bg + q;
        float xr = (q ? a01 : a00) + bi0;
        float xz = (q ? a11 : a10) + bi1;
        float xn = (q ? a21 : a20) + bi2;
        float r = 1.f / (1.f + expf(-(xr + bh0)));
        float z = 1.f / (1.f + expf(-(xz + bh1)));
        float n = tanhf(xn + r * bh2);
        float h = (1.f - z) * n;               // + z*h0, h0 = 0
        g_h[b * Hdim + j] = h;
        g_y[(size_t)b * Ktot + j] = h;
        out_h[b * Hdim + j] = h;
    }
}

// ---------------------------------------------------------------------------
// K2: u[b,e] = sum_h g_h[b,h] * attn_W[h, Hdim + e]
// ---------------------------------------------------------------------------
__global__ __launch_bounds__(256) void u_kernel(const float* __restrict__ attn_W)
{
    int idx = blockIdx.x * blockDim.x + threadIdx.x;   // 65536
    int e = idx & 1023;
    int b = idx >> 10;
    const float* W = attn_W + Hdim + e;
    const float* hb = g_h + b * Hdim;
    float a0 = 0.f, a1 = 0.f;
    #pragma unroll 8
    for (int hh = 0; hh < Hdim; hh += 2) {
        a0 += hb[hh]     * W[(size_t)hh * (Hdim + EHdim)];
        a1 += hb[hh + 1] * W[(size_t)(hh + 1) * (Hdim + EHdim)];
    }
    g_u[b * EHdim + e] = a0 + a1;
}

// ---------------------------------------------------------------------------
// K3: scores[b,s] = dot(enc[s,b,:], u[b,:])
// ---------------------------------------------------------------------------
__global__ __launch_bounds__(256) void scores_kernel(const float* __restrict__ enc)
{
    int gw   = (blockIdx.x * blockDim.x + threadIdx.x) >> 5;
    int lane = threadIdx.x & 31;
    int b = gw >> 9;
    int s = gw & 511;
    const float4* ev = (const float4*)(enc + (size_t)s * (Bdim * EHdim) + (size_t)b * EHdim);
    const float4* uv = (const float4*)(g_u + (size_t)b * EHdim);
    float acc = 0.f;
    #pragma unroll 4
    for (int t = lane; t < EHdim / 4; t += 32) {
        float4 e4 = ev[t], u4 = uv[t];
        acc += e4.x*u4.x + e4.y*u4.y + e4.z*u4.z + e4.w*u4.w;
    }
    #pragma unroll
    for (int o = 16; o; o >>= 1) acc += __shfl_xor_sync(0xffffffffu, acc, o);
    if (lane == 0) g_scores[b * Sdim + s] = acc;
}

// ---------------------------------------------------------------------------
// K4: softmax over s (512) per b
// ---------------------------------------------------------------------------
__global__ __launch_bounds__(256) void softmax_kernel(float* __restrict__ out_attn)
{
    int b = blockIdx.x, tid = threadIdx.x;
    __shared__ float red[8];
    __shared__ float bcast[2];

    float s0 = g_scores[b * Sdim + tid];
    float s1 = g_scores[b * Sdim + 256 + tid];

    float m = fmaxf(s0, s1);
    #pragma unroll
    for (int o = 16; o; o >>= 1) m = fmaxf(m, __shfl_xor_sync(0xffffffffu, m, o));
    if ((tid & 31) == 0) red[tid >> 5] = m;
    __syncthreads();
    if (tid < 32) {
        float v = (tid < 8) ? red[tid] : -FLT_MAX;
        #pragma unroll
        for (int o = 4; o; o >>= 1) v = fmaxf(v, __shfl_xor_sync(0xffffffffu, v, o));
        if (tid == 0) bcast[0] = v;
    }
    __syncthreads();
    float bm = bcast[0];

    float e0 = expf(s0 - bm), e1 = expf(s1 - bm);
    float sum = e0 + e1;
    #pragma unroll
    for (int o = 16; o; o >>= 1) sum += __shfl_xor_sync(0xffffffffu, sum, o);
    if ((tid & 31) == 0) red[tid >> 5] = sum;
    __syncthreads();
    if (tid < 32) {
        float v = (tid < 8) ? red[tid] : 0.f;
        #pragma unroll
        for (int o = 4; o; o >>= 1) v += __shfl_xor_sync(0xffffffffu, v, o);
        if (tid == 0) bcast[1] = v;
    }
    __syncthreads();
    float inv = 1.f / bcast[1];

    float w0 = e0 * inv, w1 = e1 * inv;
    g_w[b * Sdim + tid]       = w0;
    g_w[b * Sdim + 256 + tid] = w1;
    out_attn[b * Sdim + tid]       = w0;
    out_attn[b * Sdim + 256 + tid] = w1;
}

// ---------------------------------------------------------------------------
// K5: context[b,e] = sum_s w[b,s] * enc[s,b,e]
// ---------------------------------------------------------------------------
__global__ __launch_bounds__(256) void context_kernel(const float* __restrict__ enc)
{
    int idx = blockIdx.x * blockDim.x + threadIdx.x;   // 65536
    int b = idx >> 10;
    int e = idx & 1023;
    const float* wrow = g_w + b * Sdim;
    const float* ep   = enc + (size_t)b * EHdim + e;
    float a0 = 0.f, a1 = 0.f;
    #pragma unroll 4
    for (int s = 0; s < Sdim; s += 2) {
        a0 += wrow[s]     * ep[(size_t)s * (Bdim * EHdim)];
        a1 += wrow[s + 1] * ep[(size_t)(s + 1) * (Bdim * EHdim)];
    }
    g_y[(size_t)b * Ktot + Hdim + e] = a0 + a1;
}

// ---------------------------------------------------------------------------
// K6: dec = y @ out_W^T + out_b via mma.sync tf32 (m16n8k8), cp.async pipeline.
// CTA: D[192 v x 64 b]; 8 warps as 4(M) x 2(N); warp tile 48x32 (3 mt x 4 nt).
// K = 2048 in 64 chunks of 32, double-buffered; 2 CTAs/SM.
// Grid = 262 CTAs <= 296 co-resident slots -> EXACTLY ONE WAVE.
// Logical-k remap: fragment k (tig, tig+4) <- global k (2*tig, 2*tig+1), same
// map for A and B => result identical; every fragment pair is one LDS.64.
// RSTR=40 (== 8 mod 32) -> conflict-free STS / LDS.64.
// Registers: acc 48 + a 12 + bf 8 = 68 fragments -> no spill under 128-cap.
// ---------------------------------------------------------------------------
#define DEC_M     192
#define DEC_KC    32
#define DEC_NCH   (Ktot / DEC_KC)       // 64
#define RSTR      40                    // padded row stride (floats)
#define AWORDS    (DEC_M * RSTR)        // 7680
#define BWORDS    (Bdim * RSTR)         // 2560
#define BUFWORDS  (AWORDS + BWORDS)     // 10240
#define DEC_SMEM  (2 * BUFWORDS * 4)    // 81920 bytes

__global__ __launch_bounds__(256, 2) void dec_kernel(
    const float* __restrict__ out_W, const float* __restrict__ out_b,
    float* __restrict__ dec)
{
    extern __shared__ float smf[];
    const uint32_t sb = smem_to_u32(smf);

    const int tx   = threadIdx.x;
    const int wid  = tx >> 5;
    const int lane = tx & 31;
    const int gid  = lane >> 2;      // 0..7
    const int tig  = lane & 3;       // 0..3
    const int wm   = wid & 3;        // 4 warps across M
    const int wn   = wid >> 2;       // 2 warps across N
    const int rb   = wm * 48;        // warp M base (48 rows)
    const int bb   = wn * 32;        // warp N base (32 cols)
    const int vb   = blockIdx.x * DEC_M;

    float acc[3][4][4];
    #pragma unroll
    for (int mt = 0; mt < 3; mt++)
        #pragma unroll
        for (int nt = 0; nt < 4; nt++)
            #pragma unroll
            for (int i = 0; i < 4; i++) acc[mt][nt][i] = 0.f;

    auto stage = [&](int c, int buf) {
        const int k0 = c * DEC_KC;
        const uint32_t base = sb + (uint32_t)buf * BUFWORDS * 4;
        #pragma unroll
        for (int i = 0; i < 6; i++) {            // A: 192 rows x 8 quads
            int idx = tx + 256 * i;
            int r = idx >> 3, q = idx & 7;
            int v = vb + r;
            int vc = v < Vdim ? v : (Vdim - 1);
            const float* src = out_W + (size_t)vc * Ktot + k0 + 4 * q;
            uint32_t dst = base + (uint32_t)(r * RSTR + 4 * q) * 4;
            cp_async16_zfill(dst, src, v < Vdim ? 16 : 0);
        }
        #pragma unroll
        for (int i = 0; i < 2; i++) {            // B: 64 rows x 8 quads
            int idx = tx + 256 * i;
            int r = idx >> 3, q = idx & 7;
            const float* src = g_y + (size_t)r * Ktot + k0 + 4 * q;
            uint32_t dst = base + (uint32_t)(AWORDS + r * RSTR + 4 * q) * 4;
            cp_async16(dst, src);
        }
    };

    stage(0, 0);
    CP_COMMIT();

    for (int c = 0; c < DEC_NCH; c++) {
        const int buf = c & 1;
        if (c + 1 < DEC_NCH) {
            stage(c + 1, (c + 1) & 1);
            CP_COMMIT();
            CP_WAIT(1);
        } else {
            CP_WAIT(0);
        }
        __syncthreads();

        const float* As = smf + buf * BUFWORDS;
        const float* Bs = As + AWORDS;
        #pragma unroll
        for (int ks = 0; ks < 4; ks++) {
            const int k = ks * 8;
            uint32_t a[3][4], bf[4][2];
            #pragma unroll
            for (int mt = 0; mt < 3; mt++) {
                int row = rb + mt * 16 + gid;
                uint2 lo = *(const uint2*)(As + row * RSTR + k + 2 * tig);
                uint2 hi = *(const uint2*)(As + (row + 8) * RSTR + k + 2 * tig);
                a[mt][0] = lo.x; a[mt][2] = lo.y;   // logical k = tig, tig+4
                a[mt][1] = hi.x; a[mt][3] = hi.y;
            }
            #pragma unroll
            for (int nt = 0; nt < 4; nt++) {
                int bc = bb + nt * 8 + gid;
                uint2 bv = *(const uint2*)(Bs + bc * RSTR + k + 2 * tig);
                bf[nt][0] = bv.x; bf[nt][1] = bv.y;
            }
            #pragma unroll
            for (int mt = 0; mt < 3; mt++)
                #pragma unroll
                for (int nt = 0; nt < 4; nt++)
                    mma_tf32(acc[mt][nt], a[mt], bf[nt]);
        }
        __syncthreads();
    }

    // ---- epilogue ----
    #pragma unroll
    for (int mt = 0; mt < 3; mt++) {
        int v0 = vb + rb + mt * 16 + gid;
        int v1 = v0 + 8;
        float bias0 = (v0 < Vdim) ? out_b[v0] : 0.f;
        float bias1 = (v1 < Vdim) ? out_b[v1] : 0.f;
        #pragma unroll
        for (int nt = 0; nt < 4; nt++) {
            int b0 = bb + nt * 8 + 2 * tig;
            int b1 = b0 + 1;
            if (v0 < Vdim) {
                dec[(size_t)b0 * Vdim + v0] = acc[mt][nt][0] + bias0;
                dec[(size_t)b1 * Vdim + v0] = acc[mt][nt][1] + bias0;
            }
            if (v1 < Vdim) {
                dec[(size_t)b0 * Vdim + v1] = acc[mt][nt][2] + bias1;
                dec[(size_t)b1 * Vdim + v1] = acc[mt][nt][3] + bias1;
            }
        }
    }
}

// ---------------------------------------------------------------------------
// K7: in-place log_softmax over V per row b
// ---------------------------------------------------------------------------
__global__ __launch_bounds__(512) void logsoftmax_kernel(float* __restrict__ dec)
{
    int b = blockIdx.x, tid = threadIdx.x;
    float* row = dec + (size_t)b * Vdim;
    __shared__ float red[16];
    __shared__ float bcast;

    float m = -FLT_MAX;
    for (int i = tid; i < Vdim; i += 512) m = fmaxf(m, row[i]);
    #pragma unroll
    for (int o = 16; o; o >>= 1) m = fmaxf(m, __shfl_xor_sync(0xffffffffu, m, o));
    if ((tid & 31) == 0) red[tid >> 5] = m;
    __syncthreads();
    if (tid < 32) {
        float v = (tid < 16) ? red[tid] : -FLT_MAX;
        #pragma unroll
        for (int o = 8; o; o >>= 1) v = fmaxf(v, __shfl_xor_sync(0xffffffffu, v, o));
        if (tid == 0) bcast = v;
    }
    __syncthreads();
    float bm = bcast;
    __syncthreads();

    float s = 0.f;
    for (int i = tid; i < Vdim; i += 512) s += expf(row[i] - bm);
    #pragma unroll
    for (int o = 16; o; o >>= 1) s += __shfl_xor_sync(0xffffffffu, s, o);
    if ((tid & 31) == 0) red[tid >> 5] = s;
    __syncthreads();
    if (tid < 32) {
        float v = (tid < 16) ? red[tid] : 0.f;
        #pragma unroll
        for (int o = 8; o; o >>= 1) v += __shfl_xor_sync(0xffffffffu, v, o);
        if (tid == 0) bcast = v;
    }
    __syncthreads();
    float lse = bm + logf(bcast);

    for (int i = tid; i < Vdim; i += 512) row[i] -= lse;
}

// ---------------------------------------------------------------------------
extern "C" void kernel_launch(void* const* d_in, const int* in_sizes, int n_in,
                              void* d_out, int out_size)
{
    const float* x      = (const float*)d_in[0];
    const float* enc    = (const float*)d_in[1];
    const float* W_ih   = (const float*)d_in[3];
    const float* b_ih   = (const float*)d_in[5];
    const float* b_hh   = (const float*)d_in[6];
    const float* attn_W = (const float*)d_in[7];
    const float* out_W  = (const float*)d_in[9];
    const float* out_b  = (const float*)d_in[10];

    float* out = (float*)d_out;
    const size_t OFF_H    = (size_t)Bdim * Vdim;
    const size_t OFF_ATTN = OFF_H + (size_t)Bdim * Hdim;

    cudaFuncSetAttribute(dec_kernel, cudaFuncAttributeMaxDynamicSharedMemorySize, DEC_SMEM);

    gru_kernel<<<128, 256>>>(x, W_ih, b_ih, b_hh, out + OFF_H);
    u_kernel<<<256, 256>>>(attn_W);
    scores_kernel<<<4096, 256>>>(enc);
    softmax_kernel<<<Bdim, 256>>>(out + OFF_ATTN);
    context_kernel<<<256, 256>>>(enc);
    dec_kernel<<<(Vdim + DEC_M - 1) / DEC_M, 256, DEC_SMEM>>>(out_W, out_b, out);
    logsoftmax_kernel<<<Bdim, 512>>>(out);
}

// round 9
// speedup vs baseline: 1.3962x; 1.0643x over previous
#include <cuda_runtime.h>
#include <cstdint>
#include <cfloat>

#define Sdim 512
#define Bdim 64
#define Hdim 1024
#define EHdim 1024
#define Vdim 50257
#define Ktot 2048              // H + EH

// ---- scratch (no allocations allowed) ----
__device__ float g_h[Bdim * Hdim];
__device__ float g_u[Bdim * EHdim];
__device__ float g_scores[Bdim * Sdim];
__device__ float g_w[Bdim * Sdim];
__device__ float g_y[Bdim * Ktot];   // [h | context], K-major per b

// ============================================================================
// sm_80-class PTX helpers (safe under .target sm_103 — no 'a' features)
// ============================================================================
__device__ __forceinline__ uint32_t smem_to_u32(const void* p) {
    uint32_t a;
    asm("{ .reg .u64 t; cvta.to.shared.u64 t, %1; cvt.u32.u64 %0, t; }" : "=r"(a) : "l"(p));
    return a;
}
__device__ __forceinline__ void cp_async16(uint32_t dst, const void* src) {
    asm volatile("cp.async.ca.shared.global [%0], [%1], 16;" :: "r"(dst), "l"(src));
}
__device__ __forceinline__ void cp_async16_zfill(uint32_t dst, const void* src, int src_bytes) {
    asm volatile("cp.async.ca.shared.global [%0], [%1], 16, %2;"
                 :: "r"(dst), "l"(src), "r"(src_bytes));
}
#define CP_COMMIT() asm volatile("cp.async.commit_group;" ::: "memory")
#define CP_WAIT(n)  asm volatile("cp.async.wait_group %0;" :: "n"(n) : "memory")

__device__ __forceinline__ void mma_tf32(float* c, const uint32_t* a, const uint32_t* b) {
    asm volatile("mma.sync.aligned.m16n8k8.row.col.f32.tf32.tf32.f32 "
        "{%0,%1,%2,%3}, {%4,%5,%6,%7}, {%8,%9}, {%0,%1,%2,%3};"
        : "+f"(c[0]), "+f"(c[1]), "+f"(c[2]), "+f"(c[3])
        : "r"(a[0]), "r"(a[1]), "r"(a[2]), "r"(a[3]), "r"(b[0]), "r"(b[1]));
}

// ---------------------------------------------------------------------------
// K1: GRU with h0=0 => gh = b_hh. Tiled GEMM: block = 8 j x 64 b, K via smem.
// ---------------------------------------------------------------------------
__global__ __launch_bounds__(256) void gru_kernel(
    const float* __restrict__ x, const float* __restrict__ W_ih,
    const float* __restrict__ b_ih, const float* __restrict__ b_hh,
    float* __restrict__ out_h)
{
    __shared__ float w_s[24][33];
    __shared__ float x_s[32][65];

    const int t  = threadIdx.x;
    const int j0 = blockIdx.x * 8;
    const int jj = t & 7;
    const int bg = t >> 3;

    float a00 = 0.f, a01 = 0.f, a10 = 0.f, a11 = 0.f, a20 = 0.f, a21 = 0.f;

    for (int k0 = 0; k0 < Hdim; k0 += 32) {
        if (t < 192) {
            int r = t >> 3, f4 = t & 7;
            int g = r >> 3, jl = r & 7;
            float4 w = *(const float4*)(W_ih + (size_t)(g * Hdim + j0 + jl) * Hdim + k0 + 4 * f4);
            w_s[r][4 * f4 + 0] = w.x; w_s[r][4 * f4 + 1] = w.y;
            w_s[r][4 * f4 + 2] = w.z; w_s[r][4 * f4 + 3] = w.w;
        }
        #pragma unroll
        for (int i = 0; i < 2; i++) {
            int idx = t + 256 * i;
            int b = idx >> 3, q = idx & 7;
            float4 xv = *(const float4*)(x + (size_t)b * Hdim + k0 + 4 * q);
            x_s[4 * q + 0][b] = xv.x; x_s[4 * q + 1][b] = xv.y;
            x_s[4 * q + 2][b] = xv.z; x_s[4 * q + 3][b] = xv.w;
        }
        __syncthreads();
        #pragma unroll
        for (int kk = 0; kk < 32; kk++) {
            float x0 = x_s[kk][2 * bg], x1 = x_s[kk][2 * bg + 1];
            float w0 = w_s[jj][kk], w1 = w_s[8 + jj][kk], w2 = w_s[16 + jj][kk];
            a00 += w0 * x0; a01 += w0 * x1;
            a10 += w1 * x0; a11 += w1 * x1;
            a20 += w2 * x0; a21 += w2 * x1;
        }
        __syncthreads();
    }

    int j = j0 + jj;
    float bi0 = b_ih[j], bi1 = b_ih[Hdim + j], bi2 = b_ih[2 * Hdim + j];
    float bh0 = b_hh[j], bh1 = b_hh[Hdim + j], bh2 = b_hh[2 * Hdim + j];
    #pragma unroll
    for (int q = 0; q < 2; q++) {
        int b = 2 * bg + q;
        float xr = (q ? a01 : a00) + bi0;
        float xz = (q ? a11 : a10) + bi1;
        float xn = (q ? a21 : a20) + bi2;
        float r = 1.f / (1.f + expf(-(xr + bh0)));
        float z = 1.f / (1.f + expf(-(xz + bh1)));
        float n = tanhf(xn + r * bh2);
        float h = (1.f - z) * n;               // + z*h0, h0 = 0
        g_h[b * Hdim + j] = h;
        g_y[(size_t)b * Ktot + j] = h;
        out_h[b * Hdim + j] = h;
    }
}

// ---------------------------------------------------------------------------
// K2: u[b,e] = sum_h g_h[b,h] * attn_W[h, Hdim + e]
// ---------------------------------------------------------------------------
__global__ __launch_bounds__(256) void u_kernel(const float* __restrict__ attn_W)
{
    int idx = blockIdx.x * blockDim.x + threadIdx.x;   // 65536
    int e = idx & 1023;
    int b = idx >> 10;
    const float* W = attn_W + Hdim + e;
    const float* hb = g_h + b * Hdim;
    float a0 = 0.f, a1 = 0.f;
    #pragma unroll 8
    for (int hh = 0; hh < Hdim; hh += 2) {
        a0 += hb[hh]     * W[(size_t)hh * (Hdim + EHdim)];
        a1 += hb[hh + 1] * W[(size_t)(hh + 1) * (Hdim + EHdim)];
    }
    g_u[b * EHdim + e] = a0 + a1;
}

// ---------------------------------------------------------------------------
// K3: scores[b,s] = dot(enc[s,b,:], u[b,:])
// ---------------------------------------------------------------------------
__global__ __launch_bounds__(256) void scores_kernel(const float* __restrict__ enc)
{
    int gw   = (blockIdx.x * blockDim.x + threadIdx.x) >> 5;
    int lane = threadIdx.x & 31;
    int b = gw >> 9;
    int s = gw & 511;
    const float4* ev = (const float4*)(enc + (size_t)s * (Bdim * EHdim) + (size_t)b * EHdim);
    const float4* uv = (const float4*)(g_u + (size_t)b * EHdim);
    float acc = 0.f;
    #pragma unroll 4
    for (int t = lane; t < EHdim / 4; t += 32) {
        float4 e4 = ev[t], u4 = uv[t];
        acc += e4.x*u4.x + e4.y*u4.y + e4.z*u4.z + e4.w*u4.w;
    }
    #pragma unroll
    for (int o = 16; o; o >>= 1) acc += __shfl_xor_sync(0xffffffffu, acc, o);
    if (lane == 0) g_scores[b * Sdim + s] = acc;
}

// ---------------------------------------------------------------------------
// K4: softmax over s (512) per b
// ---------------------------------------------------------------------------
__global__ __launch_bounds__(256) void softmax_kernel(float* __restrict__ out_attn)
{
    int b = blockIdx.x, tid = threadIdx.x;
    __shared__ float red[8];
    __shared__ float bcast[2];

    float s0 = g_scores[b * Sdim + tid];
    float s1 = g_scores[b * Sdim + 256 + tid];

    float m = fmaxf(s0, s1);
    #pragma unroll
    for (int o = 16; o; o >>= 1) m = fmaxf(m, __shfl_xor_sync(0xffffffffu, m, o));
    if ((tid & 31) == 0) red[tid >> 5] = m;
    __syncthreads();
    if (tid < 32) {
        float v = (tid < 8) ? red[tid] : -FLT_MAX;
        #pragma unroll
        for (int o = 4; o; o >>= 1) v = fmaxf(v, __shfl_xor_sync(0xffffffffu, v, o));
        if (tid == 0) bcast[0] = v;
    }
    __syncthreads();
    float bm = bcast[0];

    float e0 = expf(s0 - bm), e1 = expf(s1 - bm);
    float sum = e0 + e1;
    #pragma unroll
    for (int o = 16; o; o >>= 1) sum += __shfl_xor_sync(0xffffffffu, sum, o);
    if ((tid & 31) == 0) red[tid >> 5] = sum;
    __syncthreads();
    if (tid < 32) {
        float v = (tid < 8) ? red[tid] : 0.f;
        #pragma unroll
        for (int o = 4; o; o >>= 1) v += __shfl_xor_sync(0xffffffffu, v, o);
        if (tid == 0) bcast[1] = v;
    }
    __syncthreads();
    float inv = 1.f / bcast[1];

    float w0 = e0 * inv, w1 = e1 * inv;
    g_w[b * Sdim + tid]       = w0;
    g_w[b * Sdim + 256 + tid] = w1;
    out_attn[b * Sdim + tid]       = w0;
    out_attn[b * Sdim + 256 + tid] = w1;
}

// ---------------------------------------------------------------------------
// K5: context[b,e] = sum_s w[b,s] * enc[s,b,e]
// ---------------------------------------------------------------------------
__global__ __launch_bounds__(256) void context_kernel(const float* __restrict__ enc)
{
    int idx = blockIdx.x * blockDim.x + threadIdx.x;   // 65536
    int b = idx >> 10;
    int e = idx & 1023;
    const float* wrow = g_w + b * Sdim;
    const float* ep   = enc + (size_t)b * EHdim + e;
    float a0 = 0.f, a1 = 0.f;
    #pragma unroll 4
    for (int s = 0; s < Sdim; s += 2) {
        a0 += wrow[s]     * ep[(size_t)s * (Bdim * EHdim)];
        a1 += wrow[s + 1] * ep[(size_t)(s + 1) * (Bdim * EHdim)];
    }
    g_y[(size_t)b * Ktot + Hdim + e] = a0 + a1;
}

// ---------------------------------------------------------------------------
// K6: dec = y @ out_W^T + out_b via mma.sync tf32, split across K into two
// launches: ADD=false covers K [0,1024) (h part, depends only on gru) and
// writes acc + bias; ADD=true covers K [1024,2048) (context part) and does
// dec += acc. The false-half runs on a forked stream concurrent with the
// attention chain; fp32 add reassociation only (same rel_err).
// CTA: D[192 v x 64 b]; 8 warps 4(M)x2(N); warp tile 48x32; KC=32, 32 chunks;
// double-buffered cp.async; 2 CTAs/SM; grid 262 = one wave.
// Logical-k remap (LDS.64) and RSTR=40 as validated in R8.
// ---------------------------------------------------------------------------
#define DEC_M     192
#define DEC_KC    32
#define DEC_KHALF 1024
#define DEC_NCH   (DEC_KHALF / DEC_KC)  // 32 chunks per half
#define RSTR      40                    // padded row stride (floats)
#define AWORDS    (DEC_M * RSTR)        // 7680
#define BWORDS    (Bdim * RSTR)         // 2560
#define BUFWORDS  (AWORDS + BWORDS)     // 10240
#define DEC_SMEM  (2 * BUFWORDS * 4)    // 81920 bytes

template <bool ADD>
__global__ __launch_bounds__(256, 2) void dec_kernel(
    const float* __restrict__ out_W, const float* __restrict__ out_b,
    float* __restrict__ dec, int kbase)
{
    extern __shared__ float smf[];
    const uint32_t sb = smem_to_u32(smf);

    const int tx   = threadIdx.x;
    const int wid  = tx >> 5;
    const int lane = tx & 31;
    const int gid  = lane >> 2;      // 0..7
    const int tig  = lane & 3;       // 0..3
    const int wm   = wid & 3;        // 4 warps across M
    const int wn   = wid >> 2;       // 2 warps across N
    const int rb   = wm * 48;        // warp M base (48 rows)
    const int bb   = wn * 32;        // warp N base (32 cols)
    const int vb   = blockIdx.x * DEC_M;

    float acc[3][4][4];
    #pragma unroll
    for (int mt = 0; mt < 3; mt++)
        #pragma unroll
        for (int nt = 0; nt < 4; nt++)
            #pragma unroll
            for (int i = 0; i < 4; i++) acc[mt][nt][i] = 0.f;

    auto stage = [&](int c, int buf) {
        const int k0 = kbase + c * DEC_KC;
        const uint32_t base = sb + (uint32_t)buf * BUFWORDS * 4;
        #pragma unroll
        for (int i = 0; i < 6; i++) {            // A: 192 rows x 8 quads
            int idx = tx + 256 * i;
            int r = idx >> 3, q = idx & 7;
            int v = vb + r;
            int vc = v < Vdim ? v : (Vdim - 1);
            const float* src = out_W + (size_t)vc * Ktot + k0 + 4 * q;
            uint32_t dst = base + (uint32_t)(r * RSTR + 4 * q) * 4;
            cp_async16_zfill(dst, src, v < Vdim ? 16 : 0);
        }
        #pragma unroll
        for (int i = 0; i < 2; i++) {            // B: 64 rows x 8 quads
            int idx = tx + 256 * i;
            int r = idx >> 3, q = idx & 7;
            const float* src = g_y + (size_t)r * Ktot + k0 + 4 * q;
            uint32_t dst = base + (uint32_t)(AWORDS + r * RSTR + 4 * q) * 4;
            cp_async16(dst, src);
        }
    };

    stage(0, 0);
    CP_COMMIT();

    for (int c = 0; c < DEC_NCH; c++) {
        const int buf = c & 1;
        if (c + 1 < DEC_NCH) {
            stage(c + 1, (c + 1) & 1);
            CP_COMMIT();
            CP_WAIT(1);
        } else {
            CP_WAIT(0);
        }
        __syncthreads();

        const float* As = smf + buf * BUFWORDS;
        const float* Bs = As + AWORDS;
        #pragma unroll
        for (int ks = 0; ks < 4; ks++) {
            const int k = ks * 8;
            uint32_t a[3][4], bf[4][2];
            #pragma unroll
            for (int mt = 0; mt < 3; mt++) {
                int row = rb + mt * 16 + gid;
                uint2 lo = *(const uint2*)(As + row * RSTR + k + 2 * tig);
                uint2 hi = *(const uint2*)(As + (row + 8) * RSTR + k + 2 * tig);
                a[mt][0] = lo.x; a[mt][2] = lo.y;   // logical k = tig, tig+4
                a[mt][1] = hi.x; a[mt][3] = hi.y;
            }
            #pragma unroll
            for (int nt = 0; nt < 4; nt++) {
                int bc = bb + nt * 8 + gid;
                uint2 bv = *(const uint2*)(Bs + bc * RSTR + k + 2 * tig);
                bf[nt][0] = bv.x; bf[nt][1] = bv.y;
            }
            #pragma unroll
            for (int mt = 0; mt < 3; mt++)
                #pragma unroll
                for (int nt = 0; nt < 4; nt++)
                    mma_tf32(acc[mt][nt], a[mt], bf[nt]);
        }
        __syncthreads();
    }

    // ---- epilogue ----
    #pragma unroll
    for (int mt = 0; mt < 3; mt++) {
        int v0 = vb + rb + mt * 16 + gid;
        int v1 = v0 + 8;
        float bias0 = 0.f, bias1 = 0.f;
        if (!ADD) {
            bias0 = (v0 < Vdim) ? out_b[v0] : 0.f;
            bias1 = (v1 < Vdim) ? out_b[v1] : 0.f;
        }
        #pragma unroll
        for (int nt = 0; nt < 4; nt++) {
            int b0 = bb + nt * 8 + 2 * tig;
            int b1 = b0 + 1;
            if (ADD) {
                if (v0 < Vdim) {
                    dec[(size_t)b0 * Vdim + v0] += acc[mt][nt][0];
                    dec[(size_t)b1 * Vdim + v0] += acc[mt][nt][1];
                }
                if (v1 < Vdim) {
                    dec[(size_t)b0 * Vdim + v1] += acc[mt][nt][2];
                    dec[(size_t)b1 * Vdim + v1] += acc[mt][nt][3];
                }
            } else {
                if (v0 < Vdim) {
                    dec[(size_t)b0 * Vdim + v0] = acc[mt][nt][0] + bias0;
                    dec[(size_t)b1 * Vdim + v0] = acc[mt][nt][1] + bias0;
                }
                if (v1 < Vdim) {
                    dec[(size_t)b0 * Vdim + v1] = acc[mt][nt][2] + bias1;
                    dec[(size_t)b1 * Vdim + v1] = acc[mt][nt][3] + bias1;
                }
            }
        }
    }
}

// ---------------------------------------------------------------------------
// K7: in-place log_softmax over V per row b
// ---------------------------------------------------------------------------
__global__ __launch_bounds__(512) void logsoftmax_kernel(float* __restrict__ dec)
{
    int b = blockIdx.x, tid = threadIdx.x;
    float* row = dec + (size_t)b * Vdim;
    __shared__ float red[16];
    __shared__ float bcast;

    float m = -FLT_MAX;
    for (int i = tid; i < Vdim; i += 512) m = fmaxf(m, row[i]);
    #pragma unroll
    for (int o = 16; o; o >>= 1) m = fmaxf(m, __shfl_xor_sync(0xffffffffu, m, o));
    if ((tid & 31) == 0) red[tid >> 5] = m;
    __syncthreads();
    if (tid < 32) {
        float v = (tid < 16) ? red[tid] : -FLT_MAX;
        #pragma unroll
        for (int o = 8; o; o >>= 1) v = fmaxf(v, __shfl_xor_sync(0xffffffffu, v, o));
        if (tid == 0) bcast = v;
    }
    __syncthreads();
    float bm = bcast;
    __syncthreads();

    float s = 0.f;
    for (int i = tid; i < Vdim; i += 512) s += expf(row[i] - bm);
    #pragma unroll
    for (int o = 16; o; o >>= 1) s += __shfl_xor_sync(0xffffffffu, s, o);
    if ((tid & 31) == 0) red[tid >> 5] = s;
    __syncthreads();
    if (tid < 32) {
        float v = (tid < 16) ? red[tid] : 0.f;
        #pragma unroll
        for (int o = 8; o; o >>= 1) v += __shfl_xor_sync(0xffffffffu, v, o);
        if (tid == 0) bcast = v;
    }
    __syncthreads();
    float lse = bm + logf(bcast);

    for (int i = tid; i < Vdim; i += 512) row[i] -= lse;
}

// ---------------------------------------------------------------------------
extern "C" void kernel_launch(void* const* d_in, const int* in_sizes, int n_in,
                              void* d_out, int out_size)
{
    const float* x      = (const float*)d_in[0];
    const float* enc    = (const float*)d_in[1];
    const float* W_ih   = (const float*)d_in[3];
    const float* b_ih   = (const float*)d_in[5];
    const float* b_hh   = (const float*)d_in[6];
    const float* attn_W = (const float*)d_in[7];
    const float* out_W  = (const float*)d_in[9];
    const float* out_b  = (const float*)d_in[10];

    float* out = (float*)d_out;
    const size_t OFF_H    = (size_t)Bdim * Vdim;
    const size_t OFF_ATTN = OFF_H + (size_t)Bdim * Hdim;
    const int DEC_GRID = (Vdim + DEC_M - 1) / DEC_M;   // 262

    cudaFuncSetAttribute(dec_kernel<false>, cudaFuncAttributeMaxDynamicSharedMemorySize, DEC_SMEM);
    cudaFuncSetAttribute(dec_kernel<true>,  cudaFuncAttributeMaxDynamicSharedMemorySize, DEC_SMEM);

    // Fork: dec's h-half (K 0..1024) depends only on gru; run it on a side
    // stream concurrent with the attention chain. Join before the context-half.
    cudaStream_t s2;
    cudaEvent_t ev_gru, ev_dech;
    cudaStreamCreateWithFlags(&s2, cudaStreamNonBlocking);
    cudaEventCreateWithFlags(&ev_gru,  cudaEventDisableTiming);
    cudaEventCreateWithFlags(&ev_dech, cudaEventDisableTiming);

    gru_kernel<<<128, 256>>>(x, W_ih, b_ih, b_hh, out + OFF_H);
    cudaEventRecord(ev_gru, 0);
    cudaStreamWaitEvent(s2, ev_gru, 0);
    dec_kernel<false><<<DEC_GRID, 256, DEC_SMEM, s2>>>(out_W, out_b, out, 0);
    cudaEventRecord(ev_dech, s2);

    u_kernel<<<256, 256>>>(attn_W);
    scores_kernel<<<4096, 256>>>(enc);
    softmax_kernel<<<Bdim, 256>>>(out + OFF_ATTN);
    context_kernel<<<256, 256>>>(enc);

    cudaStreamWaitEvent(0, ev_dech, 0);   // join fork before the += half
    dec_kernel<true><<<DEC_GRID, 256, DEC_SMEM>>>(out_W, out_b, out, 1024);
    logsoftmax_kernel<<<Bdim, 512>>>(out);
}